// round 5
// baseline (speedup 1.0000x reference)
#include <cuda_runtime.h>
#include <math.h>
#include <stdint.h>

#define DM    1024
#define DFF   4096
#define SQ    2048
#define BATCH 2
#define ROWS  (BATCH*SQ)   /* 4096 */
#define DK    64
#define NH    16
#define DM3   (3*DM)

// ---------------- scratch (device globals; no allocation) ----------------
__device__ float g_xn  [ROWS*DM];
__device__ float g_qkv [ROWS*DM3];
__device__ float g_ctx [ROWS*DM];
__device__ float g_x1  [ROWS*DM];
__device__ float g_h   [ROWS*DFF];
__device__ float g_wqkv[DM*DM3];
__device__ float g_bqkv[DM3];
__device__ float g_wr  [DM*DM + DM*DFF + DFF*DM];   // rounded wo|w1|w2

// ---------------- helpers -------------------------------------------------
__device__ __forceinline__ uint32_t cvtrna(float f) {
    uint32_t u; asm("cvt.rna.tf32.f32 %0, %1;" : "=r"(u) : "f"(f)); return u;
}
__device__ __forceinline__ float rndtf(float f) {
    return __uint_as_float(cvtrna(f));
}
__device__ __forceinline__ void mma8(float* c,
    uint32_t a0, uint32_t a1, uint32_t a2, uint32_t a3,
    uint32_t b0, uint32_t b1)
{
    asm volatile(
      "mma.sync.aligned.m16n8k8.row.col.f32.tf32.tf32.f32 "
      "{%0,%1,%2,%3},{%4,%5,%6,%7},{%8,%9},{%0,%1,%2,%3};"
      : "+f"(c[0]), "+f"(c[1]), "+f"(c[2]), "+f"(c[3])
      : "r"(a0), "r"(a1), "r"(a2), "r"(a3), "r"(b0), "r"(b1));
}
__device__ __forceinline__ uint32_t s2u(const void* p) {
    uint32_t a;
    asm("{.reg .u64 t; cvta.to.shared.u64 t, %1; cvt.u32.u64 %0, t;}"
        : "=r"(a) : "l"(p));
    return a;
}
__device__ __forceinline__ void cpasync16(uint32_t dst, const void* src) {
    asm volatile("cp.async.cg.shared.global [%0], [%1], 16;" :: "r"(dst), "l"(src));
}
#define CP_COMMIT() asm volatile("cp.async.commit_group;")
#define CP_WAIT2()  asm volatile("cp.async.wait_group 2;")
#define CP_WAIT0()  asm volatile("cp.async.wait_group 0;")

// ---------------- fused round-copy: wo|w1|w2 -> tf32 RNA ------------------
#define NW4_WO (DM*DM/4)
#define NW4_W1 (DM*DFF/4)
#define NW4_W2 (DFF*DM/4)
__global__ void __launch_bounds__(256) round_all(
    const float* __restrict__ wo, const float* __restrict__ w1,
    const float* __restrict__ w2, float* __restrict__ dst)
{
    int i = blockIdx.x * 256 + threadIdx.x;
    const float* src;
    int local;
    if (i < NW4_WO)                   { src = wo; local = i; }
    else if (i < NW4_WO + NW4_W1)     { src = w1; local = i - NW4_WO; }
    else if (i < NW4_WO + NW4_W1 + NW4_W2) { src = w2; local = i - NW4_WO - NW4_W1; }
    else return;
    float4 v = *(const float4*)(src + (size_t)local*4);
    v.x = rndtf(v.x); v.y = rndtf(v.y); v.z = rndtf(v.z); v.w = rndtf(v.w);
    *(float4*)(dst + (size_t)i*4) = v;
}

// ---------------- pack wq|wk|wv -> [1024][3072] (rounded), biases ---------
__global__ void __launch_bounds__(256) pack_qkv(
    const float* __restrict__ wq, const float* __restrict__ wk,
    const float* __restrict__ wv, const float* __restrict__ bq,
    const float* __restrict__ bk, const float* __restrict__ bv,
    float* __restrict__ W, float* __restrict__ B)
{
    const int NW = 3 * (DM*DM/4);
    int idx = blockIdx.x * 256 + threadIdx.x;
    if (idx < NW) {
        int m  = idx / (DM*DM/4);
        int r  = idx - m * (DM*DM/4);
        int k  = r >> 8;
        int j4 = r & 255;
        const float* src = (m == 0) ? wq : (m == 1) ? wk : wv;
        float4 v = *(const float4*)(src + k*DM + j4*4);
        v.x = rndtf(v.x); v.y = rndtf(v.y); v.z = rndtf(v.z); v.w = rndtf(v.w);
        *(float4*)(W + (size_t)k*DM3 + m*DM + j4*4) = v;
    } else if (idx < NW + 3*256) {
        int i = idx - NW;
        int m = i >> 8, j4 = i & 255;
        const float* src = (m == 0) ? bq : (m == 1) ? bk : bv;
        *(float4*)(B + m*DM + j4*4) = *(const float4*)(src + j4*4);
    }
}

// ---------------- LayerNorm (rounded tf32 output) -------------------------
__global__ void __launch_bounds__(256) ln_kernel(
    const float* __restrict__ X, const float* __restrict__ gamma,
    const float* __restrict__ beta, float* __restrict__ Y)
{
    const int row = blockIdx.x, tid = threadIdx.x;
    const float* xr = X + (size_t)row * DM;
    float4 xv = *(const float4*)(xr + tid*4);
    float s  = xv.x + xv.y + xv.z + xv.w;
    float s2 = xv.x*xv.x + xv.y*xv.y + xv.z*xv.z + xv.w*xv.w;
    #pragma unroll
    for (int o = 16; o; o >>= 1) {
        s  += __shfl_xor_sync(0xffffffffu, s,  o);
        s2 += __shfl_xor_sync(0xffffffffu, s2, o);
    }
    __shared__ float sm1[8], sm2[8];
    if ((tid & 31) == 0) { sm1[tid>>5] = s; sm2[tid>>5] = s2; }
    __syncthreads();
    float ts = 0.f, ts2 = 0.f;
    #pragma unroll
    for (int i = 0; i < 8; i++) { ts += sm1[i]; ts2 += sm2[i]; }
    float mean = ts * (1.0f / DM);
    float var  = (ts2 - ts * mean) * (1.0f / (DM - 1));   // unbiased (ddof=1)
    float inv  = 1.0f / (sqrtf(var) + 1e-6f);             // eps OUTSIDE sqrt
    float4 g4 = *(const float4*)(gamma + tid*4);
    float4 b4 = *(const float4*)(beta  + tid*4);
    float4 y;
    y.x = rndtf(g4.x * (xv.x - mean) * inv + b4.x);
    y.y = rndtf(g4.y * (xv.y - mean) * inv + b4.y);
    y.z = rndtf(g4.z * (xv.z - mean) * inv + b4.z);
    y.w = rndtf(g4.w * (xv.w - mean) * inv + b4.w);
    *(float4*)(Y + (size_t)row * DM + tid*4) = y;
}

// ---------------- tf32 GEMM 256x128x16, 4-stage ring, 64x64 warp tile -----
// C = A@B + bias ; EPI: 0=round(tf32), 1=relu+round, 2=+residual (no round)
// 256 thr = 8 warps (4m x 2n). Per k16-step: 64 LDS + 64 MMA (1.0 ratio),
// single __syncthreads per step.
#define BM 256
#define BN 128
#define BK 16
#define NSTAGE 4
#define GA_STRIDE 20
#define GB_STRIDE 136
#define GA_FLOATS (BM*GA_STRIDE)            /* 5120 */
#define GB_FLOATS (BK*GB_STRIDE)            /* 2176 */
#define GEMM_SMEM (NSTAGE*(GA_FLOATS + GB_FLOATS)*4)   /* 116736 B */

template<int EPI>
__global__ void __launch_bounds__(256) gemm_tc(
    const float* __restrict__ A, const float* __restrict__ Bm,
    const float* __restrict__ bias, const float* __restrict__ res,
    float* __restrict__ C, int M, int N, int K)
{
    extern __shared__ float gsm[];
    float* As = gsm;                          // [NSTAGE][GA_FLOATS]
    float* Bs = gsm + NSTAGE*GA_FLOATS;       // [NSTAGE][GB_FLOATS]

    const int tid  = threadIdx.x;
    const int lane = tid & 31, wid = tid >> 5;
    const int wm = wid >> 1, wn = wid & 1;    // 4 x 2
    const int gid = lane >> 2, tig = lane & 3;
    const int bm = blockIdx.y * BM, bn = blockIdx.x * BN;

    // A prefetch: 4 threads/row (16B each), 64 rows/warp-pass, 4 passes
    const int ar0 = tid >> 2, ac = (tid & 3) * 4;
    // B prefetch: 32 threads/row (4 floats each), 8 rows/pass, 2 passes
    const int br0 = tid >> 5, bc = (tid & 31) * 4;
    const uint32_t as_u = s2u(As);
    const uint32_t bs_u = s2u(Bs);

    const int NT = K >> 4;

    auto prefetch = [&](int kt) {
        const int buf = kt & (NSTAGE-1);
        const float* Ag = A + (size_t)(bm + ar0) * K + kt*BK + ac;
        uint32_t ad = as_u + (uint32_t)(buf*GA_FLOATS + ar0*GA_STRIDE + ac) * 4;
        #pragma unroll
        for (int i = 0; i < 4; i++)
            cpasync16(ad + (uint32_t)(i*64*GA_STRIDE*4), Ag + (size_t)(i*64)*K);
        const float* Bg = Bm + (size_t)(kt*BK + br0) * N + bn + bc;
        uint32_t bd = bs_u + (uint32_t)(buf*GB_FLOATS + br0*GB_STRIDE + bc) * 4;
        #pragma unroll
        for (int i = 0; i < 2; i++)
            cpasync16(bd + (uint32_t)(i*8*GB_STRIDE*4), Bg + (size_t)(i*8)*N);
    };

    float acc[4][8][4];
    #pragma unroll
    for (int a = 0; a < 4; a++)
        #pragma unroll
        for (int b = 0; b < 8; b++)
            #pragma unroll
            for (int c = 0; c < 4; c++) acc[a][b][c] = 0.f;

    prefetch(0); CP_COMMIT();
    if (NT > 1) prefetch(1); CP_COMMIT();
    if (NT > 2) prefetch(2); CP_COMMIT();

    for (int kt = 0; kt < NT; kt++) {
        CP_WAIT2();                 // stage kt retired (<=2 groups in flight)
        __syncthreads();            // all warps done with stage (kt-1)%4 too
        const float* Ab = As + (kt & (NSTAGE-1)) * GA_FLOATS;
        const float* Bb = Bs + (kt & (NSTAGE-1)) * GB_FLOATS;
        #pragma unroll
        for (int ks = 0; ks < 2; ks++) {
            const int c = ks*8 + tig;
            uint32_t af[4][4];
            #pragma unroll
            for (int mt = 0; mt < 4; mt++) {
                const int r = wm*64 + mt*16 + gid;
                af[mt][0] = __float_as_uint(Ab[r*GA_STRIDE + c]);
                af[mt][1] = __float_as_uint(Ab[(r+8)*GA_STRIDE + c]);
                af[mt][2] = __float_as_uint(Ab[r*GA_STRIDE + c + 4]);
                af[mt][3] = __float_as_uint(Ab[(r+8)*GA_STRIDE + c + 4]);
            }
            #pragma unroll
            for (int nt = 0; nt < 8; nt++) {
                const int cn = wn*64 + nt*8 + gid;
                uint32_t b0 = __float_as_uint(Bb[(ks*8 + tig)*GB_STRIDE + cn]);
                uint32_t b1 = __float_as_uint(Bb[(ks*8 + tig + 4)*GB_STRIDE + cn]);
                #pragma unroll
                for (int mt = 0; mt < 4; mt++)
                    mma8(acc[mt][nt], af[mt][0], af[mt][1], af[mt][2], af[mt][3], b0, b1);
            }
        }
        if (kt + 3 < NT) prefetch(kt + 3);
        CP_COMMIT();                // keep group numbering aligned
    }

    #pragma unroll
    for (int mt = 0; mt < 4; mt++) {
        const int r0 = bm + wm*64 + mt*16 + gid;
        #pragma unroll
        for (int nt = 0; nt < 8; nt++) {
            const int cn = bn + wn*64 + nt*8 + tig*2;
            float bx = bias[cn], by = bias[cn+1];
            float2 v0 = make_float2(acc[mt][nt][0] + bx, acc[mt][nt][1] + by);
            float2 v1 = make_float2(acc[mt][nt][2] + bx, acc[mt][nt][3] + by);
            size_t o0 = (size_t)r0 * N + cn;
            size_t o1 = o0 + (size_t)8 * N;
            if (EPI == 0) {
                v0.x = rndtf(v0.x); v0.y = rndtf(v0.y);
                v1.x = rndtf(v1.x); v1.y = rndtf(v1.y);
            }
            if (EPI == 1) {
                v0.x = rndtf(fmaxf(v0.x, 0.f)); v0.y = rndtf(fmaxf(v0.y, 0.f));
                v1.x = rndtf(fmaxf(v1.x, 0.f)); v1.y = rndtf(fmaxf(v1.y, 0.f));
            }
            if (EPI == 2) {
                float2 r0v = *(const float2*)(res + o0);
                float2 r1v = *(const float2*)(res + o1);
                v0.x += r0v.x; v0.y += r0v.y;
                v1.x += r1v.x; v1.y += r1v.y;
            }
            *(float2*)(C + o0) = v0;
            *(float2*)(C + o1) = v1;
        }
    }
}

// ---------------- tensor-core flash attention (tf32, lean) ----------------
#define QSTR 68
#define KSTR 68
#define VSTR 72
#define PSTR 68
#define ATT_Q (64*QSTR)
#define ATT_K (64*KSTR)        /* == 4 warps * 16*PSTR : P aliases K */
#define ATT_V (64*VSTR)
#define ATT_SMEM ((ATT_Q + ATT_K + ATT_V + 64) * 4)

__global__ void __launch_bounds__(128) attn_tc(
    const float* __restrict__ QKV, const int* __restrict__ mask,
    float* __restrict__ O)
{
    extern __shared__ uint32_t smu[];
    uint32_t* q_s = smu;
    uint32_t* k_s = q_s + ATT_Q;    // aliased with P after QK phase
    uint32_t* v_s = k_s + ATT_K;
    int*      m_s = (int*)(v_s + ATT_V);

    const int tid = threadIdx.x, lane = tid & 31, w = tid >> 5;
    const int gid = lane >> 2, tig = lane & 3;
    const int qt = blockIdx.x, h = blockIdx.y, b = blockIdx.z;
    const float* Qp = QKV + (size_t)b * SQ * DM3 + (size_t)h * DK;
    const float* Kp = Qp + DM;
    const float* Vp = Qp + 2*DM;
    const uint32_t ks_u = s2u(k_s);
    const uint32_t vs_u = s2u(v_s);

    auto kv_prefetch = [&](int t) {
        #pragma unroll
        for (int i = 0; i < 8; i++) {
            int c = tid + i*128;
            int r = c >> 4, c4 = c & 15;
            size_t goff = (size_t)(t*64 + r) * DM3 + c4*4;
            cpasync16(ks_u + (uint32_t)(r*KSTR + c4*4)*4, Kp + goff);
            cpasync16(vs_u + (uint32_t)(r*VSTR + c4*4)*4, Vp + goff);
        }
    };

    kv_prefetch(0); CP_COMMIT();

    for (int i = tid; i < 64*16; i += 128) {
        int r = i >> 4, c4 = i & 15;
        float4 qv = *(const float4*)(Qp + (size_t)(qt*64 + r) * DM3 + c4*4);
        *(uint4*)&q_s[r*QSTR + c4*4] = *(uint4*)&qv;
    }

    float o[8][4];
    #pragma unroll
    for (int nt = 0; nt < 8; nt++)
        #pragma unroll
        for (int i = 0; i < 4; i++) o[nt][i] = 0.f;
    float l0 = 0.f, l1 = 0.f;
    uint32_t* pw = k_s + w * (16*PSTR);
    const int NTI = SQ/64;

    for (int t = 0; t < NTI; t++) {
        if (tid < 64) m_s[tid] = mask[b*SQ + t*64 + tid];
        CP_WAIT0();
        __syncthreads();

        float s[8][4];
        #pragma unroll
        for (int nt = 0; nt < 8; nt++)
            #pragma unroll
            for (int i = 0; i < 4; i++) s[nt][i] = 0.f;
        const int qr = w*16 + gid;
        #pragma unroll
        for (int ks = 0; ks < 8; ks++) {
            const int c = ks*8 + tig;
            uint32_t a0 = q_s[qr*QSTR + c];
            uint32_t a1 = q_s[(qr+8)*QSTR + c];
            uint32_t a2 = q_s[qr*QSTR + c + 4];
            uint32_t a3 = q_s[(qr+8)*QSTR + c + 4];
            #pragma unroll
            for (int nt = 0; nt < 8; nt++) {
                uint32_t b0 = k_s[(nt*8 + gid)*KSTR + c];
                uint32_t b1 = k_s[(nt*8 + gid)*KSTR + c + 4];
                mma8(s[nt], a0, a1, a2, a3, b0, b1);
            }
        }
        __syncthreads();

        #pragma unroll
        for (int nt = 0; nt < 8; nt++) {
            const int c0 = nt*8 + tig*2;
            const bool z0 = (m_s[c0] == 0), z1 = (m_s[c0+1] == 0);
            float p0 = __expf(z0 ? -1e9f : s[nt][0] * 0.125f);
            float p1 = __expf(z1 ? -1e9f : s[nt][1] * 0.125f);
            float p2 = __expf(z0 ? -1e9f : s[nt][2] * 0.125f);
            float p3 = __expf(z1 ? -1e9f : s[nt][3] * 0.125f);
            uint32_t u0 = cvtrna(p0), u1 = cvtrna(p1);
            uint32_t u2 = cvtrna(p2), u3 = cvtrna(p3);
            l0 += __uint_as_float(u0) + __uint_as_float(u1);
            l1 += __uint_as_float(u2) + __uint_as_float(u3);
            pw[gid*PSTR + c0]       = u0;
            pw[gid*PSTR + c0 + 1]   = u1;
            pw[(gid+8)*PSTR + c0]   = u2;
            pw[(gid+8)*PSTR + c0+1] = u3;
        }
        __syncwarp();

        #pragma unroll
        for (int ks = 0; ks < 8; ks++) {
            const int c = ks*8 + tig;
            uint32_t a0 = pw[gid*PSTR + c];
            uint32_t a1 = pw[(gid+8)*PSTR + c];
            uint32_t a2 = pw[gid*PSTR + c + 4];
            uint32_t a3 = pw[(gid+8)*PSTR + c + 4];
            #pragma unroll
            for (int nt = 0; nt < 8; nt++) {
                uint32_t b0 = v_s[(ks*8 + tig)*VSTR + nt*8 + gid];
                uint32_t b1 = v_s[(ks*8 + tig + 4)*VSTR + nt*8 + gid];
                mma8(o[nt], a0, a1, a2, a3, b0, b1);
            }
        }
        __syncthreads();
        if (t + 1 < NTI) kv_prefetch(t + 1);
        CP_COMMIT();
    }

    l0 += __shfl_xor_sync(0xffffffffu, l0, 1);
    l0 += __shfl_xor_sync(0xffffffffu, l0, 2);
    l1 += __shfl_xor_sync(0xffffffffu, l1, 1);
    l1 += __shfl_xor_sync(0xffffffffu, l1, 2);
    const float n0 = 1.0f / l0, n1 = 1.0f / l1;
    #pragma unroll
    for (int nt = 0; nt < 8; nt++) {
        const int cn = h*DK + nt*8 + tig*2;
        size_t r0 = (size_t)(b*SQ + qt*64 + w*16 + gid) * DM + cn;
        size_t r1 = r0 + (size_t)8 * DM;
        *(float2*)(O + r0) = make_float2(rndtf(o[nt][0]*n0), rndtf(o[nt][1]*n0));
        *(float2*)(O + r1) = make_float2(rndtf(o[nt][2]*n1), rndtf(o[nt][3]*n1));
    }
}

// --------------------------------------------------------------------------
extern "C" void kernel_launch(void* const* d_in, const int* in_sizes, int n_in,
                              void* d_out, int out_size)
{
    const float* x    = (const float*)d_in[0];
    const int*   mask = (const int*)  d_in[1];
    const float* wq = (const float*)d_in[2],  *bq = (const float*)d_in[3];
    const float* wk = (const float*)d_in[4],  *bk = (const float*)d_in[5];
    const float* wv = (const float*)d_in[6],  *bv = (const float*)d_in[7];
    const float* wo = (const float*)d_in[8],  *bo = (const float*)d_in[9];
    const float* w1 = (const float*)d_in[10], *b1 = (const float*)d_in[11];
    const float* w2 = (const float*)d_in[12], *b2 = (const float*)d_in[13];
    const float* g1 = (const float*)d_in[14], *be1 = (const float*)d_in[15];
    const float* g2 = (const float*)d_in[16], *be2 = (const float*)d_in[17];
    float* out = (float*)d_out;

    float *xn, *qkv, *ctx, *x1, *hbuf, *Wq, *Bq, *Wr;
    cudaGetSymbolAddress((void**)&xn,   g_xn);
    cudaGetSymbolAddress((void**)&qkv,  g_qkv);
    cudaGetSymbolAddress((void**)&ctx,  g_ctx);
    cudaGetSymbolAddress((void**)&x1,   g_x1);
    cudaGetSymbolAddress((void**)&hbuf, g_h);
    cudaGetSymbolAddress((void**)&Wq,   g_wqkv);
    cudaGetSymbolAddress((void**)&Bq,   g_bqkv);
    cudaGetSymbolAddress((void**)&Wr,   g_wr);
    float* wo_r = Wr;
    float* w1_r = Wr + DM*DM;
    float* w2_r = Wr + DM*DM + DM*DFF;

    cudaFuncSetAttribute(gemm_tc<0>, cudaFuncAttributeMaxDynamicSharedMemorySize, GEMM_SMEM);
    cudaFuncSetAttribute(gemm_tc<1>, cudaFuncAttributeMaxDynamicSharedMemorySize, GEMM_SMEM);
    cudaFuncSetAttribute(gemm_tc<2>, cudaFuncAttributeMaxDynamicSharedMemorySize, GEMM_SMEM);
    cudaFuncSetAttribute(attn_tc,    cudaFuncAttributeMaxDynamicSharedMemorySize, ATT_SMEM);

    dim3 gQKV(DM3/BN, ROWS/BM);      // 24 x 16
    dim3 gProj(DM/BN,  ROWS/BM);     // 8 x 16
    dim3 gFF1 (DFF/BN, ROWS/BM);     // 32 x 16

    // 0) weight prep (rounded tf32)
    pack_qkv<<<(3*(DM*DM/4) + 3*256 + 255)/256, 256>>>(wq, wk, wv, bq, bk, bv, Wq, Bq);
    round_all<<<((NW4_WO + NW4_W1 + NW4_W2) + 255)/256, 256>>>(wo, w1, w2, Wr);
    // 1) LN1
    ln_kernel<<<ROWS, 256>>>(x, g1, be1, xn);
    // 2) fused QKV projection (rounded output)
    gemm_tc<0><<<gQKV, 256, GEMM_SMEM>>>(xn, Wq, Bq, nullptr, qkv, ROWS, DM3, DM);
    // 3) fused masked flash attention -> ctx (rounded)
    attn_tc<<<dim3(SQ/64, NH, BATCH), 128, ATT_SMEM>>>(qkv, mask, ctx);
    // 4) out-proj + residual(x) -> x1
    gemm_tc<2><<<gProj, 256, GEMM_SMEM>>>(ctx, wo_r, bo, x, x1, ROWS, DM, DM);
    // 5) LN2
    ln_kernel<<<ROWS, 256>>>(x1, g2, be2, xn);
    // 6) FFN up + relu (rounded output)
    gemm_tc<1><<<gFF1, 256, GEMM_SMEM>>>(xn, w1_r, b1, nullptr, hbuf, ROWS, DFF, DM);
    // 7) FFN down + residual(x1) -> out
    gemm_tc<2><<<gProj, 256, GEMM_SMEM>>>(hbuf, w2_r, b2, x1, out, ROWS, DM, DFF);
}

// round 6
// speedup vs baseline: 1.0946x; 1.0946x over previous
#include <cuda_runtime.h>
#include <math.h>
#include <stdint.h>

#define DM    1024
#define DFF   4096
#define SQ    2048
#define BATCH 2
#define ROWS  (BATCH*SQ)   /* 4096 */
#define DK    64
#define NH    16
#define DM3   (3*DM)

// ---------------- scratch (device globals; no allocation) ----------------
__device__ float g_xn  [ROWS*DM];
__device__ float g_qkv [ROWS*DM3];
__device__ float g_ctx [ROWS*DM];
__device__ float g_x1  [ROWS*DM];
__device__ float g_h   [ROWS*DFF];
__device__ float g_wqkv[DM*DM3];
__device__ float g_bqkv[DM3];
__device__ float g_wr  [DM*DM + DM*DFF + DFF*DM];   // rounded wo|w1|w2

// ---------------- helpers -------------------------------------------------
__device__ __forceinline__ uint32_t cvtrna(float f) {
    uint32_t u; asm("cvt.rna.tf32.f32 %0, %1;" : "=r"(u) : "f"(f)); return u;
}
__device__ __forceinline__ float rndtf(float f) {
    return __uint_as_float(cvtrna(f));
}
__device__ __forceinline__ void mma8(float* c,
    uint32_t a0, uint32_t a1, uint32_t a2, uint32_t a3,
    uint32_t b0, uint32_t b1)
{
    asm volatile(
      "mma.sync.aligned.m16n8k8.row.col.f32.tf32.tf32.f32 "
      "{%0,%1,%2,%3},{%4,%5,%6,%7},{%8,%9},{%0,%1,%2,%3};"
      : "+f"(c[0]), "+f"(c[1]), "+f"(c[2]), "+f"(c[3])
      : "r"(a0), "r"(a1), "r"(a2), "r"(a3), "r"(b0), "r"(b1));
}
__device__ __forceinline__ uint32_t s2u(const void* p) {
    uint32_t a;
    asm("{.reg .u64 t; cvta.to.shared.u64 t, %1; cvt.u32.u64 %0, t;}"
        : "=r"(a) : "l"(p));
    return a;
}
__device__ __forceinline__ void cpasync16(uint32_t dst, const void* src) {
    asm volatile("cp.async.cg.shared.global [%0], [%1], 16;" :: "r"(dst), "l"(src));
}
#define CP_COMMIT() asm volatile("cp.async.commit_group;")
#define CP_WAIT1()  asm volatile("cp.async.wait_group 1;")
#define CP_WAIT0()  asm volatile("cp.async.wait_group 0;")

// ---------------- fused round-copy: wo|w1|w2 -> tf32 RNA ------------------
#define NW4_WO (DM*DM/4)
#define NW4_W1 (DM*DFF/4)
#define NW4_W2 (DFF*DM/4)
__global__ void __launch_bounds__(256) round_all(
    const float* __restrict__ wo, const float* __restrict__ w1,
    const float* __restrict__ w2, float* __restrict__ dst)
{
    int i = blockIdx.x * 256 + threadIdx.x;
    const float* src;
    int local;
    if (i < NW4_WO)                   { src = wo; local = i; }
    else if (i < NW4_WO + NW4_W1)     { src = w1; local = i - NW4_WO; }
    else if (i < NW4_WO + NW4_W1 + NW4_W2) { src = w2; local = i - NW4_WO - NW4_W1; }
    else return;
    float4 v = *(const float4*)(src + (size_t)local*4);
    v.x = rndtf(v.x); v.y = rndtf(v.y); v.z = rndtf(v.z); v.w = rndtf(v.w);
    *(float4*)(dst + (size_t)i*4) = v;
}

// ---------------- pack wq|wk|wv -> [1024][3072] (rounded), biases ---------
__global__ void __launch_bounds__(256) pack_qkv(
    const float* __restrict__ wq, const float* __restrict__ wk,
    const float* __restrict__ wv, const float* __restrict__ bq,
    const float* __restrict__ bk, const float* __restrict__ bv,
    float* __restrict__ W, float* __restrict__ B)
{
    const int NW = 3 * (DM*DM/4);
    int idx = blockIdx.x * 256 + threadIdx.x;
    if (idx < NW) {
        int m  = idx / (DM*DM/4);
        int r  = idx - m * (DM*DM/4);
        int k  = r >> 8;
        int j4 = r & 255;
        const float* src = (m == 0) ? wq : (m == 1) ? wk : wv;
        float4 v = *(const float4*)(src + k*DM + j4*4);
        v.x = rndtf(v.x); v.y = rndtf(v.y); v.z = rndtf(v.z); v.w = rndtf(v.w);
        *(float4*)(W + (size_t)k*DM3 + m*DM + j4*4) = v;
    } else if (idx < NW + 3*256) {
        int i = idx - NW;
        int m = i >> 8, j4 = i & 255;
        const float* src = (m == 0) ? bq : (m == 1) ? bk : bv;
        *(float4*)(B + m*DM + j4*4) = *(const float4*)(src + j4*4);
    }
}

// ---------------- LayerNorm (rounded tf32 output) -------------------------
__global__ void __launch_bounds__(256) ln_kernel(
    const float* __restrict__ X, const float* __restrict__ gamma,
    const float* __restrict__ beta, float* __restrict__ Y)
{
    const int row = blockIdx.x, tid = threadIdx.x;
    const float* xr = X + (size_t)row * DM;
    float4 xv = *(const float4*)(xr + tid*4);
    float s  = xv.x + xv.y + xv.z + xv.w;
    float s2 = xv.x*xv.x + xv.y*xv.y + xv.z*xv.z + xv.w*xv.w;
    #pragma unroll
    for (int o = 16; o; o >>= 1) {
        s  += __shfl_xor_sync(0xffffffffu, s,  o);
        s2 += __shfl_xor_sync(0xffffffffu, s2, o);
    }
    __shared__ float sm1[8], sm2[8];
    if ((tid & 31) == 0) { sm1[tid>>5] = s; sm2[tid>>5] = s2; }
    __syncthreads();
    float ts = 0.f, ts2 = 0.f;
    #pragma unroll
    for (int i = 0; i < 8; i++) { ts += sm1[i]; ts2 += sm2[i]; }
    float mean = ts * (1.0f / DM);
    float var  = (ts2 - ts * mean) * (1.0f / (DM - 1));   // unbiased (ddof=1)
    float inv  = 1.0f / (sqrtf(var) + 1e-6f);             // eps OUTSIDE sqrt
    float4 g4 = *(const float4*)(gamma + tid*4);
    float4 b4 = *(const float4*)(beta  + tid*4);
    float4 y;
    y.x = rndtf(g4.x * (xv.x - mean) * inv + b4.x);
    y.y = rndtf(g4.y * (xv.y - mean) * inv + b4.y);
    y.z = rndtf(g4.z * (xv.z - mean) * inv + b4.z);
    y.w = rndtf(g4.w * (xv.w - mean) * inv + b4.w);
    *(float4*)(Y + (size_t)row * DM + tid*4) = y;
}

// ---------------- tf32 GEMM 128x128x32, 4 warps, 64x64 warp tile ----------
// C = A@B + bias ; EPI: 0=round(tf32), 1=relu+round, 2=+residual (no round)
// 128 thr = 4 warps (2m x 2n), 64x64 per warp. 1.0 LDS/MMA, 2 CTAs/SM.
// A smem stride 36 (== 4 mod 32 -> conflict-free frag loads); B stride 136.
#define BK 32
#define GA_STRIDE 36
#define GB_STRIDE 136
#define GA_FLOATS (128*GA_STRIDE)           /* 4608 */
#define GB_FLOATS (BK*GB_STRIDE)            /* 4352 */
#define GEMM_SMEM (2*(GA_FLOATS + GB_FLOATS)*4)   /* 71680 B */

template<int EPI>
__global__ void __launch_bounds__(128, 2) gemm_tc(
    const float* __restrict__ A, const float* __restrict__ Bm,
    const float* __restrict__ bias, const float* __restrict__ res,
    float* __restrict__ C, int M, int N, int K)
{
    extern __shared__ float gsm[];
    float* As = gsm;                          // [2][GA_FLOATS]
    float* Bs = gsm + 2*GA_FLOATS;            // [2][GB_FLOATS]

    const int tid  = threadIdx.x;
    const int lane = tid & 31, wid = tid >> 5;
    const int wm = wid >> 1, wn = wid & 1;    // 2 x 2
    const int gid = lane >> 2, tig = lane & 3;
    const int bm = blockIdx.y * 128, bn = blockIdx.x * 128;

    // A prefetch: 8 threads/row, 16 rows/pass, 8 passes
    const int ar0 = tid >> 3, ac = (tid & 7) * 4;
    // B prefetch: 32 threads/row, 4 rows/pass, 8 passes
    const int br0 = tid >> 5, bc = (tid & 31) * 4;
    const uint32_t as_u = s2u(As);
    const uint32_t bs_u = s2u(Bs);

    const int NT = K >> 5;

    auto prefetch = [&](int kt, int buf) {
        const float* Ag = A + (size_t)(bm + ar0) * K + kt*BK + ac;
        uint32_t ad = as_u + (uint32_t)(buf*GA_FLOATS + ar0*GA_STRIDE + ac) * 4;
        #pragma unroll
        for (int i = 0; i < 8; i++)
            cpasync16(ad + (uint32_t)(i*16*GA_STRIDE*4), Ag + (size_t)(i*16)*K);
        const float* Bg = Bm + (size_t)(kt*BK + br0) * N + bn + bc;
        uint32_t bd = bs_u + (uint32_t)(buf*GB_FLOATS + br0*GB_STRIDE + bc) * 4;
        #pragma unroll
        for (int i = 0; i < 8; i++)
            cpasync16(bd + (uint32_t)(i*4*GB_STRIDE*4), Bg + (size_t)(i*4)*N);
    };

    float acc[4][8][4];
    #pragma unroll
    for (int a = 0; a < 4; a++)
        #pragma unroll
        for (int b = 0; b < 8; b++)
            #pragma unroll
            for (int c = 0; c < 4; c++) acc[a][b][c] = 0.f;

    prefetch(0, 0); CP_COMMIT();
    if (NT > 1) prefetch(1, 1);
    CP_COMMIT();

    for (int kt = 0; kt < NT; kt++) {
        CP_WAIT1();
        __syncthreads();
        const float* Ab = As + (kt & 1) * GA_FLOATS;
        const float* Bb = Bs + (kt & 1) * GB_FLOATS;
        #pragma unroll
        for (int ks = 0; ks < 4; ks++) {
            const int c = ks*8 + tig;
            uint32_t af[4][4];
            #pragma unroll
            for (int mt = 0; mt < 4; mt++) {
                const int r = wm*64 + mt*16 + gid;
                af[mt][0] = __float_as_uint(Ab[r*GA_STRIDE + c]);
                af[mt][1] = __float_as_uint(Ab[(r+8)*GA_STRIDE + c]);
                af[mt][2] = __float_as_uint(Ab[r*GA_STRIDE + c + 4]);
                af[mt][3] = __float_as_uint(Ab[(r+8)*GA_STRIDE + c + 4]);
            }
            #pragma unroll
            for (int nt = 0; nt < 8; nt++) {
                const int cn = wn*64 + nt*8 + gid;
                uint32_t b0 = __float_as_uint(Bb[(ks*8 + tig)*GB_STRIDE + cn]);
                uint32_t b1 = __float_as_uint(Bb[(ks*8 + tig + 4)*GB_STRIDE + cn]);
                #pragma unroll
                for (int mt = 0; mt < 4; mt++)
                    mma8(acc[mt][nt], af[mt][0], af[mt][1], af[mt][2], af[mt][3], b0, b1);
            }
        }
        __syncthreads();
        if (kt + 2 < NT) prefetch(kt + 2, kt & 1);
        CP_COMMIT();
    }

    #pragma unroll
    for (int mt = 0; mt < 4; mt++) {
        const int r0 = bm + wm*64 + mt*16 + gid;
        #pragma unroll
        for (int nt = 0; nt < 8; nt++) {
            const int cn = bn + wn*64 + nt*8 + tig*2;
            float bx = bias[cn], by = bias[cn+1];
            float2 v0 = make_float2(acc[mt][nt][0] + bx, acc[mt][nt][1] + by);
            float2 v1 = make_float2(acc[mt][nt][2] + bx, acc[mt][nt][3] + by);
            size_t o0 = (size_t)r0 * N + cn;
            size_t o1 = o0 + (size_t)8 * N;
            if (EPI == 0) {
                v0.x = rndtf(v0.x); v0.y = rndtf(v0.y);
                v1.x = rndtf(v1.x); v1.y = rndtf(v1.y);
            }
            if (EPI == 1) {
                v0.x = rndtf(fmaxf(v0.x, 0.f)); v0.y = rndtf(fmaxf(v0.y, 0.f));
                v1.x = rndtf(fmaxf(v1.x, 0.f)); v1.y = rndtf(fmaxf(v1.y, 0.f));
            }
            if (EPI == 2) {
                float2 r0v = *(const float2*)(res + o0);
                float2 r1v = *(const float2*)(res + o1);
                v0.x += r0v.x; v0.y += r0v.y;
                v1.x += r1v.x; v1.y += r1v.y;
            }
            *(float2*)(C + o0) = v0;
            *(float2*)(C + o1) = v1;
        }
    }
}

// ---------------- tensor-core flash attention (tf32, lean) ----------------
#define QSTR 68
#define KSTR 68
#define VSTR 72
#define PSTR 68
#define ATT_Q (64*QSTR)
#define ATT_K (64*KSTR)        /* == 4 warps * 16*PSTR : P aliases K */
#define ATT_V (64*VSTR)
#define ATT_SMEM ((ATT_Q + ATT_K + ATT_V + 64) * 4)

__global__ void __launch_bounds__(128) attn_tc(
    const float* __restrict__ QKV, const int* __restrict__ mask,
    float* __restrict__ O)
{
    extern __shared__ uint32_t smu[];
    uint32_t* q_s = smu;
    uint32_t* k_s = q_s + ATT_Q;    // aliased with P after QK phase
    uint32_t* v_s = k_s + ATT_K;
    int*      m_s = (int*)(v_s + ATT_V);

    const int tid = threadIdx.x, lane = tid & 31, w = tid >> 5;
    const int gid = lane >> 2, tig = lane & 3;
    const int qt = blockIdx.x, h = blockIdx.y, b = blockIdx.z;
    const float* Qp = QKV + (size_t)b * SQ * DM3 + (size_t)h * DK;
    const float* Kp = Qp + DM;
    const float* Vp = Qp + 2*DM;
    const uint32_t ks_u = s2u(k_s);
    const uint32_t vs_u = s2u(v_s);

    auto kv_prefetch = [&](int t) {
        #pragma unroll
        for (int i = 0; i < 8; i++) {
            int c = tid + i*128;
            int r = c >> 4, c4 = c & 15;
            size_t goff = (size_t)(t*64 + r) * DM3 + c4*4;
            cpasync16(ks_u + (uint32_t)(r*KSTR + c4*4)*4, Kp + goff);
            cpasync16(vs_u + (uint32_t)(r*VSTR + c4*4)*4, Vp + goff);
        }
    };

    kv_prefetch(0); CP_COMMIT();

    for (int i = tid; i < 64*16; i += 128) {
        int r = i >> 4, c4 = i & 15;
        float4 qv = *(const float4*)(Qp + (size_t)(qt*64 + r) * DM3 + c4*4);
        *(uint4*)&q_s[r*QSTR + c4*4] = *(uint4*)&qv;
    }

    float o[8][4];
    #pragma unroll
    for (int nt = 0; nt < 8; nt++)
        #pragma unroll
        for (int i = 0; i < 4; i++) o[nt][i] = 0.f;
    float l0 = 0.f, l1 = 0.f;
    uint32_t* pw = k_s + w * (16*PSTR);
    const int NTI = SQ/64;

    for (int t = 0; t < NTI; t++) {
        if (tid < 64) m_s[tid] = mask[b*SQ + t*64 + tid];
        CP_WAIT0();
        __syncthreads();

        float s[8][4];
        #pragma unroll
        for (int nt = 0; nt < 8; nt++)
            #pragma unroll
            for (int i = 0; i < 4; i++) s[nt][i] = 0.f;
        const int qr = w*16 + gid;
        #pragma unroll
        for (int ks = 0; ks < 8; ks++) {
            const int c = ks*8 + tig;
            uint32_t a0 = q_s[qr*QSTR + c];
            uint32_t a1 = q_s[(qr+8)*QSTR + c];
            uint32_t a2 = q_s[qr*QSTR + c + 4];
            uint32_t a3 = q_s[(qr+8)*QSTR + c + 4];
            #pragma unroll
            for (int nt = 0; nt < 8; nt++) {
                uint32_t b0 = k_s[(nt*8 + gid)*KSTR + c];
                uint32_t b1 = k_s[(nt*8 + gid)*KSTR + c + 4];
                mma8(s[nt], a0, a1, a2, a3, b0, b1);
            }
        }
        __syncthreads();

        #pragma unroll
        for (int nt = 0; nt < 8; nt++) {
            const int c0 = nt*8 + tig*2;
            const bool z0 = (m_s[c0] == 0), z1 = (m_s[c0+1] == 0);
            float p0 = __expf(z0 ? -1e9f : s[nt][0] * 0.125f);
            float p1 = __expf(z1 ? -1e9f : s[nt][1] * 0.125f);
            float p2 = __expf(z0 ? -1e9f : s[nt][2] * 0.125f);
            float p3 = __expf(z1 ? -1e9f : s[nt][3] * 0.125f);
            uint32_t u0 = cvtrna(p0), u1 = cvtrna(p1);
            uint32_t u2 = cvtrna(p2), u3 = cvtrna(p3);
            l0 += __uint_as_float(u0) + __uint_as_float(u1);
            l1 += __uint_as_float(u2) + __uint_as_float(u3);
            pw[gid*PSTR + c0]       = u0;
            pw[gid*PSTR + c0 + 1]   = u1;
            pw[(gid+8)*PSTR + c0]   = u2;
            pw[(gid+8)*PSTR + c0+1] = u3;
        }
        __syncwarp();

        #pragma unroll
        for (int ks = 0; ks < 8; ks++) {
            const int c = ks*8 + tig;
            uint32_t a0 = pw[gid*PSTR + c];
            uint32_t a1 = pw[(gid+8)*PSTR + c];
            uint32_t a2 = pw[gid*PSTR + c + 4];
            uint32_t a3 = pw[(gid+8)*PSTR + c + 4];
            #pragma unroll
            for (int nt = 0; nt < 8; nt++) {
                uint32_t b0 = v_s[(ks*8 + tig)*VSTR + nt*8 + gid];
                uint32_t b1 = v_s[(ks*8 + tig + 4)*VSTR + nt*8 + gid];
                mma8(o[nt], a0, a1, a2, a3, b0, b1);
            }
        }
        __syncthreads();
        if (t + 1 < NTI) kv_prefetch(t + 1);
        CP_COMMIT();
    }

    l0 += __shfl_xor_sync(0xffffffffu, l0, 1);
    l0 += __shfl_xor_sync(0xffffffffu, l0, 2);
    l1 += __shfl_xor_sync(0xffffffffu, l1, 1);
    l1 += __shfl_xor_sync(0xffffffffu, l1, 2);
    const float n0 = 1.0f / l0, n1 = 1.0f / l1;
    #pragma unroll
    for (int nt = 0; nt < 8; nt++) {
        const int cn = h*DK + nt*8 + tig*2;
        size_t r0 = (size_t)(b*SQ + qt*64 + w*16 + gid) * DM + cn;
        size_t r1 = r0 + (size_t)8 * DM;
        *(float2*)(O + r0) = make_float2(rndtf(o[nt][0]*n0), rndtf(o[nt][1]*n0));
        *(float2*)(O + r1) = make_float2(rndtf(o[nt][2]*n1), rndtf(o[nt][3]*n1));
    }
}

// --------------------------------------------------------------------------
extern "C" void kernel_launch(void* const* d_in, const int* in_sizes, int n_in,
                              void* d_out, int out_size)
{
    const float* x    = (const float*)d_in[0];
    const int*   mask = (const int*)  d_in[1];
    const float* wq = (const float*)d_in[2],  *bq = (const float*)d_in[3];
    const float* wk = (const float*)d_in[4],  *bk = (const float*)d_in[5];
    const float* wv = (const float*)d_in[6],  *bv = (const float*)d_in[7];
    const float* wo = (const float*)d_in[8],  *bo = (const float*)d_in[9];
    const float* w1 = (const float*)d_in[10], *b1 = (const float*)d_in[11];
    const float* w2 = (const float*)d_in[12], *b2 = (const float*)d_in[13];
    const float* g1 = (const float*)d_in[14], *be1 = (const float*)d_in[15];
    const float* g2 = (const float*)d_in[16], *be2 = (const float*)d_in[17];
    float* out = (float*)d_out;

    float *xn, *qkv, *ctx, *x1, *hbuf, *Wq, *Bq, *Wr;
    cudaGetSymbolAddress((void**)&xn,   g_xn);
    cudaGetSymbolAddress((void**)&qkv,  g_qkv);
    cudaGetSymbolAddress((void**)&ctx,  g_ctx);
    cudaGetSymbolAddress((void**)&x1,   g_x1);
    cudaGetSymbolAddress((void**)&hbuf, g_h);
    cudaGetSymbolAddress((void**)&Wq,   g_wqkv);
    cudaGetSymbolAddress((void**)&Bq,   g_bqkv);
    cudaGetSymbolAddress((void**)&Wr,   g_wr);
    float* wo_r = Wr;
    float* w1_r = Wr + DM*DM;
    float* w2_r = Wr + DM*DM + DM*DFF;

    cudaFuncSetAttribute(gemm_tc<0>, cudaFuncAttributeMaxDynamicSharedMemorySize, GEMM_SMEM);
    cudaFuncSetAttribute(gemm_tc<1>, cudaFuncAttributeMaxDynamicSharedMemorySize, GEMM_SMEM);
    cudaFuncSetAttribute(gemm_tc<2>, cudaFuncAttributeMaxDynamicSharedMemorySize, GEMM_SMEM);
    cudaFuncSetAttribute(attn_tc,    cudaFuncAttributeMaxDynamicSharedMemorySize, ATT_SMEM);

    dim3 gQKV(DM3/128, ROWS/128);    // 24 x 32
    dim3 gProj(DM/128,  ROWS/128);   // 8 x 32
    dim3 gFF1 (DFF/128, ROWS/128);   // 32 x 32

    // 0) weight prep (rounded tf32)
    pack_qkv<<<(3*(DM*DM/4) + 3*256 + 255)/256, 256>>>(wq, wk, wv, bq, bk, bv, Wq, Bq);
    round_all<<<((NW4_WO + NW4_W1 + NW4_W2) + 255)/256, 256>>>(wo, w1, w2, Wr);
    // 1) LN1
    ln_kernel<<<ROWS, 256>>>(x, g1, be1, xn);
    // 2) fused QKV projection (rounded output)
    gemm_tc<0><<<gQKV, 128, GEMM_SMEM>>>(xn, Wq, Bq, nullptr, qkv, ROWS, DM3, DM);
    // 3) fused masked flash attention -> ctx (rounded)
    attn_tc<<<dim3(SQ/64, NH, BATCH), 128, ATT_SMEM>>>(qkv, mask, ctx);
    // 4) out-proj + residual(x) -> x1
    gemm_tc<2><<<gProj, 128, GEMM_SMEM>>>(ctx, wo_r, bo, x, x1, ROWS, DM, DM);
    // 5) LN2
    ln_kernel<<<ROWS, 256>>>(x1, g2, be2, xn);
    // 6) FFN up + relu (rounded output)
    gemm_tc<1><<<gFF1, 128, GEMM_SMEM>>>(xn, w1_r, b1, nullptr, hbuf, ROWS, DFF, DM);
    // 7) FFN down + residual(x1) -> out
    gemm_tc<2><<<gProj, 128, GEMM_SMEM>>>(hbuf, w2_r, b2, x1, out, ROWS, DM, DFF);
}

// round 7
// speedup vs baseline: 1.6095x; 1.4704x over previous
#include <cuda_runtime.h>
#include <cuda_fp16.h>
#include <math.h>
#include <stdint.h>

#define DM    1024
#define DFF   4096
#define SQ    2048
#define BATCH 2
#define ROWS  (BATCH*SQ)   /* 4096 */
#define DK    64
#define NH    16
#define DM3   (3*DM)

// ---------------- scratch (device globals; no allocation) ----------------
__device__ __half g_xn_h [ROWS*DM];
__device__ float  g_qkv  [ROWS*DM3];
__device__ __half g_ctx_h[ROWS*DM];
__device__ float  g_x1   [ROWS*DM];
__device__ __half g_h_h  [ROWS*DFF];
__device__ __half g_wqkvh[DM*DM3];
__device__ float  g_bqkv [DM3];
__device__ __half g_wrh  [DM*DM + DM*DFF + DFF*DM];   // half wo|w1|w2

// ---------------- helpers -------------------------------------------------
__device__ __forceinline__ uint32_t cvtrna(float f) {
    uint32_t u; asm("cvt.rna.tf32.f32 %0, %1;" : "=r"(u) : "f"(f)); return u;
}
__device__ __forceinline__ float rndtf(float f) {
    return __uint_as_float(cvtrna(f));
}
// tf32 mma (attention)
__device__ __forceinline__ void mma8(float* c,
    uint32_t a0, uint32_t a1, uint32_t a2, uint32_t a3,
    uint32_t b0, uint32_t b1)
{
    asm volatile(
      "mma.sync.aligned.m16n8k8.row.col.f32.tf32.tf32.f32 "
      "{%0,%1,%2,%3},{%4,%5,%6,%7},{%8,%9},{%0,%1,%2,%3};"
      : "+f"(c[0]), "+f"(c[1]), "+f"(c[2]), "+f"(c[3])
      : "r"(a0), "r"(a1), "r"(a2), "r"(a3), "r"(b0), "r"(b1));
}
// fp16 mma (GEMMs)
__device__ __forceinline__ void mma16(float* c,
    uint32_t a0, uint32_t a1, uint32_t a2, uint32_t a3,
    uint32_t b0, uint32_t b1)
{
    asm volatile(
      "mma.sync.aligned.m16n8k16.row.col.f32.f16.f16.f32 "
      "{%0,%1,%2,%3},{%4,%5,%6,%7},{%8,%9},{%0,%1,%2,%3};"
      : "+f"(c[0]), "+f"(c[1]), "+f"(c[2]), "+f"(c[3])
      : "r"(a0), "r"(a1), "r"(a2), "r"(a3), "r"(b0), "r"(b1));
}
__device__ __forceinline__ void ldsm_x4(uint32_t& r0, uint32_t& r1,
                                        uint32_t& r2, uint32_t& r3, uint32_t addr)
{
    asm volatile("ldmatrix.sync.aligned.m8n8.x4.shared.b16 {%0,%1,%2,%3}, [%4];"
                 : "=r"(r0), "=r"(r1), "=r"(r2), "=r"(r3) : "r"(addr));
}
__device__ __forceinline__ void ldsm_x4_t(uint32_t& r0, uint32_t& r1,
                                          uint32_t& r2, uint32_t& r3, uint32_t addr)
{
    asm volatile("ldmatrix.sync.aligned.m8n8.x4.trans.shared.b16 {%0,%1,%2,%3}, [%4];"
                 : "=r"(r0), "=r"(r1), "=r"(r2), "=r"(r3) : "r"(addr));
}
__device__ __forceinline__ uint32_t s2u(const void* p) {
    uint32_t a;
    asm("{.reg .u64 t; cvta.to.shared.u64 t, %1; cvt.u32.u64 %0, t;}"
        : "=r"(a) : "l"(p));
    return a;
}
__device__ __forceinline__ void cpasync16(uint32_t dst, const void* src) {
    asm volatile("cp.async.cg.shared.global [%0], [%1], 16;" :: "r"(dst), "l"(src));
}
#define CP_COMMIT() asm volatile("cp.async.commit_group;")
#define CP_WAIT1()  asm volatile("cp.async.wait_group 1;")
#define CP_WAIT0()  asm volatile("cp.async.wait_group 0;")

// ---------------- half-convert: wo|w1|w2 -> half --------------------------
#define NW4_WO (DM*DM/4)
#define NW4_W1 (DM*DFF/4)
#define NW4_W2 (DFF*DM/4)
__global__ void __launch_bounds__(256) half_all(
    const float* __restrict__ wo, const float* __restrict__ w1,
    const float* __restrict__ w2, __half* __restrict__ dst)
{
    int i = blockIdx.x * 256 + threadIdx.x;
    const float* src;
    int local;
    if (i < NW4_WO)                        { src = wo; local = i; }
    else if (i < NW4_WO + NW4_W1)          { src = w1; local = i - NW4_WO; }
    else if (i < NW4_WO + NW4_W1 + NW4_W2) { src = w2; local = i - NW4_WO - NW4_W1; }
    else return;
    float4 v = *(const float4*)(src + (size_t)local*4);
    __half2 h0 = __floats2half2_rn(v.x, v.y);
    __half2 h1 = __floats2half2_rn(v.z, v.w);
    *(uint2*)(dst + (size_t)i*4) = make_uint2(
        *(uint32_t*)&h0, *(uint32_t*)&h1);
}

// ---------------- pack wq|wk|wv -> half [1024][3072], biases f32 ----------
__global__ void __launch_bounds__(256) pack_qkv(
    const float* __restrict__ wq, const float* __restrict__ wk,
    const float* __restrict__ wv, const float* __restrict__ bq,
    const float* __restrict__ bk, const float* __restrict__ bv,
    __half* __restrict__ W, float* __restrict__ B)
{
    const int NW = 3 * (DM*DM/4);
    int idx = blockIdx.x * 256 + threadIdx.x;
    if (idx < NW) {
        int m  = idx / (DM*DM/4);
        int r  = idx - m * (DM*DM/4);
        int k  = r >> 8;
        int j4 = r & 255;
        const float* src = (m == 0) ? wq : (m == 1) ? wk : wv;
        float4 v = *(const float4*)(src + k*DM + j4*4);
        __half2 h0 = __floats2half2_rn(v.x, v.y);
        __half2 h1 = __floats2half2_rn(v.z, v.w);
        *(uint2*)(W + (size_t)k*DM3 + m*DM + j4*4) = make_uint2(
            *(uint32_t*)&h0, *(uint32_t*)&h1);
    } else if (idx < NW + 3*256) {
        int i = idx - NW;
        int m = i >> 8, j4 = i & 255;
        const float* src = (m == 0) ? bq : (m == 1) ? bk : bv;
        *(float4*)(B + m*DM + j4*4) = *(const float4*)(src + j4*4);
    }
}

// ---------------- LayerNorm (half output) ---------------------------------
__global__ void __launch_bounds__(256) ln_kernel(
    const float* __restrict__ X, const float* __restrict__ gamma,
    const float* __restrict__ beta, __half* __restrict__ Y)
{
    const int row = blockIdx.x, tid = threadIdx.x;
    const float* xr = X + (size_t)row * DM;
    float4 xv = *(const float4*)(xr + tid*4);
    float s  = xv.x + xv.y + xv.z + xv.w;
    float s2 = xv.x*xv.x + xv.y*xv.y + xv.z*xv.z + xv.w*xv.w;
    #pragma unroll
    for (int o = 16; o; o >>= 1) {
        s  += __shfl_xor_sync(0xffffffffu, s,  o);
        s2 += __shfl_xor_sync(0xffffffffu, s2, o);
    }
    __shared__ float sm1[8], sm2[8];
    if ((tid & 31) == 0) { sm1[tid>>5] = s; sm2[tid>>5] = s2; }
    __syncthreads();
    float ts = 0.f, ts2 = 0.f;
    #pragma unroll
    for (int i = 0; i < 8; i++) { ts += sm1[i]; ts2 += sm2[i]; }
    float mean = ts * (1.0f / DM);
    float var  = (ts2 - ts * mean) * (1.0f / (DM - 1));   // unbiased (ddof=1)
    float inv  = 1.0f / (sqrtf(var) + 1e-6f);             // eps OUTSIDE sqrt
    float4 g4 = *(const float4*)(gamma + tid*4);
    float4 b4 = *(const float4*)(beta  + tid*4);
    __half2 h0 = __floats2half2_rn(g4.x * (xv.x - mean) * inv + b4.x,
                                   g4.y * (xv.y - mean) * inv + b4.y);
    __half2 h1 = __floats2half2_rn(g4.z * (xv.z - mean) * inv + b4.z,
                                   g4.w * (xv.w - mean) * inv + b4.w);
    *(uint2*)(Y + (size_t)row * DM + tid*4) = make_uint2(
        *(uint32_t*)&h0, *(uint32_t*)&h1);
}

// ---------------- fp16 GEMM 128x128x64, ldmatrix, 4 warps 64x64 -----------
// C = A@B + bias ; EPI: 0=f32 out + tf32 round (qkv), 1=relu -> half out,
//                  2=+residual -> f32 out
#define BK 64
#define AS 72     /* halves; 144B row stride: LDSM banks 4r mod 32 */
#define BS 136    /* halves; 272B row stride */
#define A_HALVES (128*AS)   /* 9216 */
#define B_HALVES (BK*BS)    /* 8704 */
#define GEMM_SMEM (2*(A_HALVES + B_HALVES)*2)   /* 71680 B */

template<int EPI>
__global__ void __launch_bounds__(128, 2) gemm_tc(
    const __half* __restrict__ A, const __half* __restrict__ Bm,
    const float* __restrict__ bias, const float* __restrict__ res,
    void* __restrict__ Cv, int M, int N, int K)
{
    extern __shared__ __half hsm[];
    __half* As = hsm;                        // [2][A_HALVES]
    __half* Bs = hsm + 2*A_HALVES;           // [2][B_HALVES]

    const int tid  = threadIdx.x;
    const int lane = tid & 31, wid = tid >> 5;
    const int wm = wid >> 1, wn = wid & 1;   // 2 x 2
    const int gid = lane >> 2, tig = lane & 3;
    const int bm = blockIdx.y * 128, bn = blockIdx.x * 128;

    // prefetch geometry (16B = 8 halves per cp.async)
    const int ar0 = tid >> 3, ac = (tid & 7) * 8;     // A: rows ar0+16i, col ac
    const int br0 = tid >> 4, bc = (tid & 15) * 8;    // B: rows br0+8i, col bc
    const uint32_t as_u = s2u(As);
    const uint32_t bs_u = s2u(Bs);

    const int NT = K >> 6;

    auto prefetch = [&](int kt, int buf) {
        const __half* Ag = A + (size_t)(bm + ar0) * K + kt*BK + ac;
        uint32_t ad = as_u + (uint32_t)(buf*A_HALVES + ar0*AS + ac) * 2;
        #pragma unroll
        for (int i = 0; i < 8; i++)
            cpasync16(ad + (uint32_t)(i*16*AS*2), Ag + (size_t)(i*16)*K);
        const __half* Bg = Bm + (size_t)(kt*BK + br0) * N + bn + bc;
        uint32_t bd = bs_u + (uint32_t)(buf*B_HALVES + br0*BS + bc) * 2;
        #pragma unroll
        for (int i = 0; i < 8; i++)
            cpasync16(bd + (uint32_t)(i*8*BS*2), Bg + (size_t)(i*8)*N);
    };

    // ldmatrix lane addressing (bytes, relative to stage base)
    const int a_row_l = (lane & 7) + (lane & 8);      // 0..15
    const int a_kcol  = ((lane >> 4) & 1) * 8;        // 0 or 8 halves
    const uint32_t a_lane_off = (uint32_t)(((wm*64 + a_row_l) * AS + a_kcol) * 2);
    const int b_row_l = lane & 15;                    // k offset 0..15
    const int b_ncol  = ((lane >> 4) & 1) * 8;        // 0 or 8 halves
    const uint32_t b_lane_off = (uint32_t)((b_row_l * BS + wn*64 + b_ncol) * 2);

    float acc[4][8][4];
    #pragma unroll
    for (int a = 0; a < 4; a++)
        #pragma unroll
        for (int b = 0; b < 8; b++)
            #pragma unroll
            for (int c = 0; c < 4; c++) acc[a][b][c] = 0.f;

    prefetch(0, 0); CP_COMMIT();
    if (NT > 1) prefetch(1, 1);
    CP_COMMIT();

    for (int kt = 0; kt < NT; kt++) {
        CP_WAIT1();
        __syncthreads();
        const uint32_t abase = as_u + (uint32_t)((kt & 1) * A_HALVES * 2) + a_lane_off;
        const uint32_t bbase = bs_u + (uint32_t)((kt & 1) * B_HALVES * 2) + b_lane_off;
        #pragma unroll
        for (int ks = 0; ks < 4; ks++) {
            uint32_t af[4][4];
            #pragma unroll
            for (int mt = 0; mt < 4; mt++)
                ldsm_x4(af[mt][0], af[mt][1], af[mt][2], af[mt][3],
                        abase + (uint32_t)(mt*16*AS*2 + ks*32));
            #pragma unroll
            for (int p = 0; p < 4; p++) {
                uint32_t b0, b1, b2, b3;
                ldsm_x4_t(b0, b1, b2, b3,
                          bbase + (uint32_t)(ks*16*BS*2 + p*32));
                #pragma unroll
                for (int mt = 0; mt < 4; mt++) {
                    mma16(acc[mt][2*p],   af[mt][0], af[mt][1], af[mt][2], af[mt][3], b0, b1);
                    mma16(acc[mt][2*p+1], af[mt][0], af[mt][1], af[mt][2], af[mt][3], b2, b3);
                }
            }
        }
        __syncthreads();
        if (kt + 2 < NT) prefetch(kt + 2, kt & 1);
        CP_COMMIT();
    }

    // epilogue
    #pragma unroll
    for (int mt = 0; mt < 4; mt++) {
        const int r0 = bm + wm*64 + mt*16 + gid;
        #pragma unroll
        for (int nt = 0; nt < 8; nt++) {
            const int cn = bn + wn*64 + nt*8 + tig*2;
            float bx = bias[cn], by = bias[cn+1];
            float2 v0 = make_float2(acc[mt][nt][0] + bx, acc[mt][nt][1] + by);
            float2 v1 = make_float2(acc[mt][nt][2] + bx, acc[mt][nt][3] + by);
            size_t o0 = (size_t)r0 * N + cn;
            size_t o1 = o0 + (size_t)8 * N;
            if (EPI == 0) {        // f32 out, tf32-rounded (feeds tf32 attention)
                float* C = (float*)Cv;
                *(float2*)(C + o0) = make_float2(rndtf(v0.x), rndtf(v0.y));
                *(float2*)(C + o1) = make_float2(rndtf(v1.x), rndtf(v1.y));
            }
            if (EPI == 1) {        // relu -> half out
                __half* C = (__half*)Cv;
                __half2 h0 = __floats2half2_rn(fmaxf(v0.x, 0.f), fmaxf(v0.y, 0.f));
                __half2 h1 = __floats2half2_rn(fmaxf(v1.x, 0.f), fmaxf(v1.y, 0.f));
                *(uint32_t*)(C + o0) = *(uint32_t*)&h0;
                *(uint32_t*)(C + o1) = *(uint32_t*)&h1;
            }
            if (EPI == 2) {        // +residual, f32 out
                float* C = (float*)Cv;
                float2 r0v = *(const float2*)(res + o0);
                float2 r1v = *(const float2*)(res + o1);
                *(float2*)(C + o0) = make_float2(v0.x + r0v.x, v0.y + r0v.y);
                *(float2*)(C + o1) = make_float2(v1.x + r1v.x, v1.y + r1v.y);
            }
        }
    }
}

// ---------------- tensor-core flash attention (tf32, lean) ----------------
// Unchanged from R6 except ctx is written as half (feeds fp16 out-proj).
#define QSTR 68
#define KSTR 68
#define VSTR 72
#define PSTR 68
#define ATT_Q (64*QSTR)
#define ATT_K (64*KSTR)        /* == 4 warps * 16*PSTR : P aliases K */
#define ATT_V (64*VSTR)
#define ATT_SMEM ((ATT_Q + ATT_K + ATT_V + 64) * 4)

__global__ void __launch_bounds__(128) attn_tc(
    const float* __restrict__ QKV, const int* __restrict__ mask,
    __half* __restrict__ O)
{
    extern __shared__ uint32_t smu[];
    uint32_t* q_s = smu;
    uint32_t* k_s = q_s + ATT_Q;    // aliased with P after QK phase
    uint32_t* v_s = k_s + ATT_K;
    int*      m_s = (int*)(v_s + ATT_V);

    const int tid = threadIdx.x, lane = tid & 31, w = tid >> 5;
    const int gid = lane >> 2, tig = lane & 3;
    const int qt = blockIdx.x, h = blockIdx.y, b = blockIdx.z;
    const float* Qp = QKV + (size_t)b * SQ * DM3 + (size_t)h * DK;
    const float* Kp = Qp + DM;
    const float* Vp = Qp + 2*DM;
    const uint32_t ks_u = s2u(k_s);
    const uint32_t vs_u = s2u(v_s);

    auto kv_prefetch = [&](int t) {
        #pragma unroll
        for (int i = 0; i < 8; i++) {
            int c = tid + i*128;
            int r = c >> 4, c4 = c & 15;
            size_t goff = (size_t)(t*64 + r) * DM3 + c4*4;
            cpasync16(ks_u + (uint32_t)(r*KSTR + c4*4)*4, Kp + goff);
            cpasync16(vs_u + (uint32_t)(r*VSTR + c4*4)*4, Vp + goff);
        }
    };

    kv_prefetch(0); CP_COMMIT();

    for (int i = tid; i < 64*16; i += 128) {
        int r = i >> 4, c4 = i & 15;
        float4 qv = *(const float4*)(Qp + (size_t)(qt*64 + r) * DM3 + c4*4);
        *(uint4*)&q_s[r*QSTR + c4*4] = *(uint4*)&qv;
    }

    float o[8][4];
    #pragma unroll
    for (int nt = 0; nt < 8; nt++)
        #pragma unroll
        for (int i = 0; i < 4; i++) o[nt][i] = 0.f;
    float l0 = 0.f, l1 = 0.f;
    uint32_t* pw = k_s + w * (16*PSTR);
    const int NTI = SQ/64;

    for (int t = 0; t < NTI; t++) {
        if (tid < 64) m_s[tid] = mask[b*SQ + t*64 + tid];
        CP_WAIT0();
        __syncthreads();

        float s[8][4];
        #pragma unroll
        for (int nt = 0; nt < 8; nt++)
            #pragma unroll
            for (int i = 0; i < 4; i++) s[nt][i] = 0.f;
        const int qr = w*16 + gid;
        #pragma unroll
        for (int ks = 0; ks < 8; ks++) {
            const int c = ks*8 + tig;
            uint32_t a0 = q_s[qr*QSTR + c];
            uint32_t a1 = q_s[(qr+8)*QSTR + c];
            uint32_t a2 = q_s[qr*QSTR + c + 4];
            uint32_t a3 = q_s[(qr+8)*QSTR + c + 4];
            #pragma unroll
            for (int nt = 0; nt < 8; nt++) {
                uint32_t b0 = k_s[(nt*8 + gid)*KSTR + c];
                uint32_t b1 = k_s[(nt*8 + gid)*KSTR + c + 4];
                mma8(s[nt], a0, a1, a2, a3, b0, b1);
            }
        }
        __syncthreads();

        #pragma unroll
        for (int nt = 0; nt < 8; nt++) {
            const int c0 = nt*8 + tig*2;
            const bool z0 = (m_s[c0] == 0), z1 = (m_s[c0+1] == 0);
            float p0 = __expf(z0 ? -1e9f : s[nt][0] * 0.125f);
            float p1 = __expf(z1 ? -1e9f : s[nt][1] * 0.125f);
            float p2 = __expf(z0 ? -1e9f : s[nt][2] * 0.125f);
            float p3 = __expf(z1 ? -1e9f : s[nt][3] * 0.125f);
            uint32_t u0 = cvtrna(p0), u1 = cvtrna(p1);
            uint32_t u2 = cvtrna(p2), u3 = cvtrna(p3);
            l0 += __uint_as_float(u0) + __uint_as_float(u1);
            l1 += __uint_as_float(u2) + __uint_as_float(u3);
            pw[gid*PSTR + c0]       = u0;
            pw[gid*PSTR + c0 + 1]   = u1;
            pw[(gid+8)*PSTR + c0]   = u2;
            pw[(gid+8)*PSTR + c0+1] = u3;
        }
        __syncwarp();

        #pragma unroll
        for (int ks = 0; ks < 8; ks++) {
            const int c = ks*8 + tig;
            uint32_t a0 = pw[gid*PSTR + c];
            uint32_t a1 = pw[(gid+8)*PSTR + c];
            uint32_t a2 = pw[gid*PSTR + c + 4];
            uint32_t a3 = pw[(gid+8)*PSTR + c + 4];
            #pragma unroll
            for (int nt = 0; nt < 8; nt++) {
                uint32_t b0 = v_s[(ks*8 + tig)*VSTR + nt*8 + gid];
                uint32_t b1 = v_s[(ks*8 + tig + 4)*VSTR + nt*8 + gid];
                mma8(o[nt], a0, a1, a2, a3, b0, b1);
            }
        }
        __syncthreads();
        if (t + 1 < NTI) kv_prefetch(t + 1);
        CP_COMMIT();
    }

    l0 += __shfl_xor_sync(0xffffffffu, l0, 1);
    l0 += __shfl_xor_sync(0xffffffffu, l0, 2);
    l1 += __shfl_xor_sync(0xffffffffu, l1, 1);
    l1 += __shfl_xor_sync(0xffffffffu, l1, 2);
    const float n0 = 1.0f / l0, n1 = 1.0f / l1;
    #pragma unroll
    for (int nt = 0; nt < 8; nt++) {
        const int cn = h*DK + nt*8 + tig*2;
        size_t r0 = (size_t)(b*SQ + qt*64 + w*16 + gid) * DM + cn;
        size_t r1 = r0 + (size_t)8 * DM;
        __half2 h0 = __floats2half2_rn(o[nt][0]*n0, o[nt][1]*n0);
        __half2 h1 = __floats2half2_rn(o[nt][2]*n1, o[nt][3]*n1);
        *(uint32_t*)(O + r0) = *(uint32_t*)&h0;
        *(uint32_t*)(O + r1) = *(uint32_t*)&h1;
    }
}

// --------------------------------------------------------------------------
extern "C" void kernel_launch(void* const* d_in, const int* in_sizes, int n_in,
                              void* d_out, int out_size)
{
    const float* x    = (const float*)d_in[0];
    const int*   mask = (const int*)  d_in[1];
    const float* wq = (const float*)d_in[2],  *bq = (const float*)d_in[3];
    const float* wk = (const float*)d_in[4],  *bk = (const float*)d_in[5];
    const float* wv = (const float*)d_in[6],  *bv = (const float*)d_in[7];
    const float* wo = (const float*)d_in[8],  *bo = (const float*)d_in[9];
    const float* w1 = (const float*)d_in[10], *b1 = (const float*)d_in[11];
    const float* w2 = (const float*)d_in[12], *b2 = (const float*)d_in[13];
    const float* g1 = (const float*)d_in[14], *be1 = (const float*)d_in[15];
    const float* g2 = (const float*)d_in[16], *be2 = (const float*)d_in[17];
    float* out = (float*)d_out;

    __half *xn, *ctxh, *hbuf, *Wqh, *Wrh;
    float *qkv, *x1, *Bq;
    cudaGetSymbolAddress((void**)&xn,   g_xn_h);
    cudaGetSymbolAddress((void**)&qkv,  g_qkv);
    cudaGetSymbolAddress((void**)&ctxh, g_ctx_h);
    cudaGetSymbolAddress((void**)&x1,   g_x1);
    cudaGetSymbolAddress((void**)&hbuf, g_h_h);
    cudaGetSymbolAddress((void**)&Wqh,  g_wqkvh);
    cudaGetSymbolAddress((void**)&Bq,   g_bqkv);
    cudaGetSymbolAddress((void**)&Wrh,  g_wrh);
    __half* wo_h = Wrh;
    __half* w1_h = Wrh + DM*DM;
    __half* w2_h = Wrh + DM*DM + DM*DFF;

    cudaFuncSetAttribute(gemm_tc<0>, cudaFuncAttributeMaxDynamicSharedMemorySize, GEMM_SMEM);
    cudaFuncSetAttribute(gemm_tc<1>, cudaFuncAttributeMaxDynamicSharedMemorySize, GEMM_SMEM);
    cudaFuncSetAttribute(gemm_tc<2>, cudaFuncAttributeMaxDynamicSharedMemorySize, GEMM_SMEM);
    cudaFuncSetAttribute(attn_tc,    cudaFuncAttributeMaxDynamicSharedMemorySize, ATT_SMEM);

    dim3 gQKV(DM3/128, ROWS/128);    // 24 x 32
    dim3 gProj(DM/128,  ROWS/128);   // 8 x 32
    dim3 gFF1 (DFF/128, ROWS/128);   // 32 x 32

    // 0) weight prep (half)
    pack_qkv<<<(3*(DM*DM/4) + 3*256 + 255)/256, 256>>>(wq, wk, wv, bq, bk, bv, Wqh, Bq);
    half_all<<<((NW4_WO + NW4_W1 + NW4_W2) + 255)/256, 256>>>(wo, w1, w2, Wrh);
    // 1) LN1 -> half
    ln_kernel<<<ROWS, 256>>>(x, g1, be1, xn);
    // 2) fused QKV projection (fp16 mma, f32 tf32-rounded out)
    gemm_tc<0><<<gQKV, 128, GEMM_SMEM>>>(xn, Wqh, Bq, nullptr, qkv, ROWS, DM3, DM);
    // 3) fused masked flash attention (tf32) -> ctx half
    attn_tc<<<dim3(SQ/64, NH, BATCH), 128, ATT_SMEM>>>(qkv, mask, ctxh);
    // 4) out-proj + residual(x) -> x1 (f32)
    gemm_tc<2><<<gProj, 128, GEMM_SMEM>>>(ctxh, wo_h, bo, x, x1, ROWS, DM, DM);
    // 5) LN2 -> half
    ln_kernel<<<ROWS, 256>>>(x1, g2, be2, xn);
    // 6) FFN up + relu -> half
    gemm_tc<1><<<gFF1, 128, GEMM_SMEM>>>(xn, w1_h, b1, nullptr, hbuf, ROWS, DFF, DM);
    // 7) FFN down + residual(x1) -> out (f32)
    gemm_tc<2><<<gProj, 128, GEMM_SMEM>>>(hbuf, w2_h, b2, x1, out, ROWS, DM, DFF);
}

// round 8
// speedup vs baseline: 2.0250x; 1.2582x over previous
#include <cuda_runtime.h>
#include <cuda_fp16.h>
#include <math.h>
#include <stdint.h>

#define DM    1024
#define DFF   4096
#define SQ    2048
#define BATCH 2
#define ROWS  (BATCH*SQ)   /* 4096 */
#define DK    64
#define NH    16
#define DM3   (3*DM)

// ---------------- scratch (device globals; no allocation) ----------------
__device__ __half g_xn_h [ROWS*DM];
__device__ __half g_qkv_h[ROWS*DM3];
__device__ __half g_ctx_h[ROWS*DM];
__device__ float  g_x1   [ROWS*DM];
__device__ __half g_h_h  [ROWS*DFF];
__device__ __half g_wqkvh[DM*DM3];
__device__ float  g_bqkv [DM3];
__device__ __half g_wrh  [DM*DM + DM*DFF + DFF*DM];   // half wo|w1|w2

// ---------------- helpers -------------------------------------------------
__device__ __forceinline__ void mma16(float* c,
    uint32_t a0, uint32_t a1, uint32_t a2, uint32_t a3,
    uint32_t b0, uint32_t b1)
{
    asm volatile(
      "mma.sync.aligned.m16n8k16.row.col.f32.f16.f16.f32 "
      "{%0,%1,%2,%3},{%4,%5,%6,%7},{%8,%9},{%0,%1,%2,%3};"
      : "+f"(c[0]), "+f"(c[1]), "+f"(c[2]), "+f"(c[3])
      : "r"(a0), "r"(a1), "r"(a2), "r"(a3), "r"(b0), "r"(b1));
}
__device__ __forceinline__ void ldsm_x4(uint32_t& r0, uint32_t& r1,
                                        uint32_t& r2, uint32_t& r3, uint32_t addr)
{
    asm volatile("ldmatrix.sync.aligned.m8n8.x4.shared.b16 {%0,%1,%2,%3}, [%4];"
                 : "=r"(r0), "=r"(r1), "=r"(r2), "=r"(r3) : "r"(addr));
}
__device__ __forceinline__ void ldsm_x4_t(uint32_t& r0, uint32_t& r1,
                                          uint32_t& r2, uint32_t& r3, uint32_t addr)
{
    asm volatile("ldmatrix.sync.aligned.m8n8.x4.trans.shared.b16 {%0,%1,%2,%3}, [%4];"
                 : "=r"(r0), "=r"(r1), "=r"(r2), "=r"(r3) : "r"(addr));
}
__device__ __forceinline__ uint32_t s2u(const void* p) {
    uint32_t a;
    asm("{.reg .u64 t; cvta.to.shared.u64 t, %1; cvt.u32.u64 %0, t;}"
        : "=r"(a) : "l"(p));
    return a;
}
__device__ __forceinline__ void cpasync16(uint32_t dst, const void* src) {
    asm volatile("cp.async.cg.shared.global [%0], [%1], 16;" :: "r"(dst), "l"(src));
}
__device__ __forceinline__ uint32_t packh2(float a, float b) {
    __half2 h = __floats2half2_rn(a, b);
    return *(uint32_t*)&h;
}
#define CP_COMMIT() asm volatile("cp.async.commit_group;")
#define CP_WAIT1()  asm volatile("cp.async.wait_group 1;")

// ---------------- half-convert: wo|w1|w2 -> half --------------------------
#define NW4_WO (DM*DM/4)
#define NW4_W1 (DM*DFF/4)
#define NW4_W2 (DFF*DM/4)
__global__ void __launch_bounds__(256) half_all(
    const float* __restrict__ wo, const float* __restrict__ w1,
    const float* __restrict__ w2, __half* __restrict__ dst)
{
    int i = blockIdx.x * 256 + threadIdx.x;
    const float* src;
    int local;
    if (i < NW4_WO)                        { src = wo; local = i; }
    else if (i < NW4_WO + NW4_W1)          { src = w1; local = i - NW4_WO; }
    else if (i < NW4_WO + NW4_W1 + NW4_W2) { src = w2; local = i - NW4_WO - NW4_W1; }
    else return;
    float4 v = *(const float4*)(src + (size_t)local*4);
    *(uint2*)(dst + (size_t)i*4) = make_uint2(packh2(v.x, v.y), packh2(v.z, v.w));
}

// ---------------- pack wq|wk|wv -> half [1024][3072], biases f32 ----------
__global__ void __launch_bounds__(256) pack_qkv(
    const float* __restrict__ wq, const float* __restrict__ wk,
    const float* __restrict__ wv, const float* __restrict__ bq,
    const float* __restrict__ bk, const float* __restrict__ bv,
    __half* __restrict__ W, float* __restrict__ B)
{
    const int NW = 3 * (DM*DM/4);
    int idx = blockIdx.x * 256 + threadIdx.x;
    if (idx < NW) {
        int m  = idx / (DM*DM/4);
        int r  = idx - m * (DM*DM/4);
        int k  = r >> 8;
        int j4 = r & 255;
        const float* src = (m == 0) ? wq : (m == 1) ? wk : wv;
        float4 v = *(const float4*)(src + k*DM + j4*4);
        *(uint2*)(W + (size_t)k*DM3 + m*DM + j4*4) =
            make_uint2(packh2(v.x, v.y), packh2(v.z, v.w));
    } else if (idx < NW + 3*256) {
        int i = idx - NW;
        int m = i >> 8, j4 = i & 255;
        const float* src = (m == 0) ? bq : (m == 1) ? bk : bv;
        *(float4*)(B + m*DM + j4*4) = *(const float4*)(src + j4*4);
    }
}

// ---------------- LayerNorm (half output) ---------------------------------
__global__ void __launch_bounds__(256) ln_kernel(
    const float* __restrict__ X, const float* __restrict__ gamma,
    const float* __restrict__ beta, __half* __restrict__ Y)
{
    const int row = blockIdx.x, tid = threadIdx.x;
    const float* xr = X + (size_t)row * DM;
    float4 xv = *(const float4*)(xr + tid*4);
    float s  = xv.x + xv.y + xv.z + xv.w;
    float s2 = xv.x*xv.x + xv.y*xv.y + xv.z*xv.z + xv.w*xv.w;
    #pragma unroll
    for (int o = 16; o; o >>= 1) {
        s  += __shfl_xor_sync(0xffffffffu, s,  o);
        s2 += __shfl_xor_sync(0xffffffffu, s2, o);
    }
    __shared__ float sm1[8], sm2[8];
    if ((tid & 31) == 0) { sm1[tid>>5] = s; sm2[tid>>5] = s2; }
    __syncthreads();
    float ts = 0.f, ts2 = 0.f;
    #pragma unroll
    for (int i = 0; i < 8; i++) { ts += sm1[i]; ts2 += sm2[i]; }
    float mean = ts * (1.0f / DM);
    float var  = (ts2 - ts * mean) * (1.0f / (DM - 1));   // unbiased (ddof=1)
    float inv  = 1.0f / (sqrtf(var) + 1e-6f);             // eps OUTSIDE sqrt
    float4 g4 = *(const float4*)(gamma + tid*4);
    float4 b4 = *(const float4*)(beta  + tid*4);
    *(uint2*)(Y + (size_t)row * DM + tid*4) = make_uint2(
        packh2(g4.x * (xv.x - mean) * inv + b4.x,
               g4.y * (xv.y - mean) * inv + b4.y),
        packh2(g4.z * (xv.z - mean) * inv + b4.z,
               g4.w * (xv.w - mean) * inv + b4.w));
}

// ---------------- fp16 GEMM 128x128x64, ldmatrix, 4 warps 64x64 -----------
// C = A@B + bias ; EPI: 0=half out (qkv), 1=relu half out, 2=+residual f32
#define BK 64
#define AS 72     /* halves; 144B row stride */
#define BS 136    /* halves; 272B row stride */
#define A_HALVES (128*AS)
#define B_HALVES (BK*BS)
#define GEMM_SMEM (2*(A_HALVES + B_HALVES)*2)

template<int EPI>
__global__ void __launch_bounds__(128, 2) gemm_tc(
    const __half* __restrict__ A, const __half* __restrict__ Bm,
    const float* __restrict__ bias, const float* __restrict__ res,
    void* __restrict__ Cv, int M, int N, int K)
{
    extern __shared__ __half hsm[];
    __half* As = hsm;
    __half* Bs = hsm + 2*A_HALVES;

    const int tid  = threadIdx.x;
    const int lane = tid & 31, wid = tid >> 5;
    const int wm = wid >> 1, wn = wid & 1;
    const int gid = lane >> 2, tig = lane & 3;
    const int bm = blockIdx.y * 128, bn = blockIdx.x * 128;

    const int ar0 = tid >> 3, ac = (tid & 7) * 8;
    const int br0 = tid >> 4, bc = (tid & 15) * 8;
    const uint32_t as_u = s2u(As);
    const uint32_t bs_u = s2u(Bs);

    const int NT = K >> 6;

    auto prefetch = [&](int kt, int buf) {
        const __half* Ag = A + (size_t)(bm + ar0) * K + kt*BK + ac;
        uint32_t ad = as_u + (uint32_t)(buf*A_HALVES + ar0*AS + ac) * 2;
        #pragma unroll
        for (int i = 0; i < 8; i++)
            cpasync16(ad + (uint32_t)(i*16*AS*2), Ag + (size_t)(i*16)*K);
        const __half* Bg = Bm + (size_t)(kt*BK + br0) * N + bn + bc;
        uint32_t bd = bs_u + (uint32_t)(buf*B_HALVES + br0*BS + bc) * 2;
        #pragma unroll
        for (int i = 0; i < 8; i++)
            cpasync16(bd + (uint32_t)(i*8*BS*2), Bg + (size_t)(i*8)*N);
    };

    const int a_row_l = (lane & 7) + (lane & 8);
    const int a_kcol  = ((lane >> 4) & 1) * 8;
    const uint32_t a_lane_off = (uint32_t)(((wm*64 + a_row_l) * AS + a_kcol) * 2);
    const int b_row_l = lane & 15;
    const int b_ncol  = ((lane >> 4) & 1) * 8;
    const uint32_t b_lane_off = (uint32_t)((b_row_l * BS + wn*64 + b_ncol) * 2);

    float acc[4][8][4];
    #pragma unroll
    for (int a = 0; a < 4; a++)
        #pragma unroll
        for (int b = 0; b < 8; b++)
            #pragma unroll
            for (int c = 0; c < 4; c++) acc[a][b][c] = 0.f;

    prefetch(0, 0); CP_COMMIT();
    if (NT > 1) prefetch(1, 1);
    CP_COMMIT();

    for (int kt = 0; kt < NT; kt++) {
        CP_WAIT1();
        __syncthreads();
        const uint32_t abase = as_u + (uint32_t)((kt & 1) * A_HALVES * 2) + a_lane_off;
        const uint32_t bbase = bs_u + (uint32_t)((kt & 1) * B_HALVES * 2) + b_lane_off;
        #pragma unroll
        for (int ks = 0; ks < 4; ks++) {
            uint32_t af[4][4];
            #pragma unroll
            for (int mt = 0; mt < 4; mt++)
                ldsm_x4(af[mt][0], af[mt][1], af[mt][2], af[mt][3],
                        abase + (uint32_t)(mt*16*AS*2 + ks*32));
            #pragma unroll
            for (int p = 0; p < 4; p++) {
                uint32_t b0, b1, b2, b3;
                ldsm_x4_t(b0, b1, b2, b3,
                          bbase + (uint32_t)(ks*16*BS*2 + p*32));
                #pragma unroll
                for (int mt = 0; mt < 4; mt++) {
                    mma16(acc[mt][2*p],   af[mt][0], af[mt][1], af[mt][2], af[mt][3], b0, b1);
                    mma16(acc[mt][2*p+1], af[mt][0], af[mt][1], af[mt][2], af[mt][3], b2, b3);
                }
            }
        }
        __syncthreads();
        if (kt + 2 < NT) prefetch(kt + 2, kt & 1);
        CP_COMMIT();
    }

    #pragma unroll
    for (int mt = 0; mt < 4; mt++) {
        const int r0 = bm + wm*64 + mt*16 + gid;
        #pragma unroll
        for (int nt = 0; nt < 8; nt++) {
            const int cn = bn + wn*64 + nt*8 + tig*2;
            float bx = bias[cn], by = bias[cn+1];
            float2 v0 = make_float2(acc[mt][nt][0] + bx, acc[mt][nt][1] + by);
            float2 v1 = make_float2(acc[mt][nt][2] + bx, acc[mt][nt][3] + by);
            size_t o0 = (size_t)r0 * N + cn;
            size_t o1 = o0 + (size_t)8 * N;
            if (EPI == 0) {        // half out (qkv)
                __half* C = (__half*)Cv;
                *(uint32_t*)(C + o0) = packh2(v0.x, v0.y);
                *(uint32_t*)(C + o1) = packh2(v1.x, v1.y);
            }
            if (EPI == 1) {        // relu -> half out
                __half* C = (__half*)Cv;
                *(uint32_t*)(C + o0) = packh2(fmaxf(v0.x, 0.f), fmaxf(v0.y, 0.f));
                *(uint32_t*)(C + o1) = packh2(fmaxf(v1.x, 0.f), fmaxf(v1.y, 0.f));
            }
            if (EPI == 2) {        // +residual, f32 out
                float* C = (float*)Cv;
                float2 r0v = *(const float2*)(res + o0);
                float2 r1v = *(const float2*)(res + o1);
                *(float2*)(C + o0) = make_float2(v0.x + r0v.x, v0.y + r0v.y);
                *(float2*)(C + o1) = make_float2(v1.x + r1v.x, v1.y + r1v.y);
            }
        }
    }
}

// ---------------- fp16 flash attention, register-resident P ---------------
// 64 q-rows/block, 4 warps x 16 rows. Q,K,V half in smem (stride 72 halves).
// K is [n][k] -> non-trans ldsm = B operand; V is [k][n] -> trans ldsm.
// P stays in registers: S-accum fragment == PV A-fragment after half2 pack.
#define QS 72
#define AQ_H (64*QS)            /* per tile: 64 x 72 halves */
#define ATT_SMEM ((AQ_H + 2*AQ_H + 2*AQ_H) * 2 + 2*64*4)

__global__ void __launch_bounds__(128) attn_tc(
    const __half* __restrict__ QKV, const int* __restrict__ mask,
    __half* __restrict__ O)
{
    extern __shared__ __half hsm[];
    __half* q_s = hsm;
    __half* k_s = q_s + AQ_H;          // 2 stages
    __half* v_s = k_s + 2*AQ_H;        // 2 stages
    int*    m_s = (int*)(v_s + 2*AQ_H);// [2][64]

    const int tid = threadIdx.x, lane = tid & 31, w = tid >> 5;
    const int gid = lane >> 2, tig = lane & 3;
    const int qt = blockIdx.x, h = blockIdx.y, b = blockIdx.z;
    const __half* Qp = QKV + (size_t)b * SQ * DM3 + (size_t)h * DK;
    const __half* Kp = Qp + DM;
    const __half* Vp = Qp + 2*DM;
    const uint32_t qs_u = s2u(q_s);
    const uint32_t ks_u = s2u(k_s);
    const uint32_t vs_u = s2u(v_s);

    auto kv_prefetch = [&](int t, int buf) {
        #pragma unroll
        for (int i = 0; i < 4; i++) {
            int c = tid + i*128;              // 0..511
            int r = c >> 3, c8 = c & 7;
            size_t goff = (size_t)(t*64 + r) * DM3 + c8*8;
            uint32_t soff = (uint32_t)((buf*AQ_H + r*QS + c8*8) * 2);
            cpasync16(ks_u + soff, Kp + goff);
            cpasync16(vs_u + soff, Vp + goff);
        }
    };

    kv_prefetch(0, 0); CP_COMMIT();

    // Q tile 64x64 halves
    for (int i = tid; i < 64*8; i += 128) {
        int r = i >> 3, c8 = i & 7;
        *(uint4*)&q_s[r*QS + c8*8] =
            *(const uint4*)(Qp + (size_t)(qt*64 + r) * DM3 + c8*8);
    }

    // ldsm lane addressing
    const int a_row_l = (lane & 7) + (lane & 8);
    const int a_kcol  = ((lane >> 4) & 1) * 8;
    const uint32_t q_lane = (uint32_t)(((w*16 + a_row_l) * QS + a_kcol) * 2);
    const int b_row_l = lane & 15;
    const int b_col_l = ((lane >> 4) & 1) * 8;

    float o[8][4];
    #pragma unroll
    for (int nt = 0; nt < 8; nt++)
        #pragma unroll
        for (int i = 0; i < 4; i++) o[nt][i] = 0.f;
    float l0 = 0.f, l1 = 0.f;
    const int NTI = SQ/64;

    for (int t = 0; t < NTI; t++) {
        if (t + 1 < NTI) kv_prefetch(t + 1, (t + 1) & 1);
        CP_COMMIT();
        if (tid < 64) m_s[(t & 1)*64 + tid] = mask[b*SQ + t*64 + tid];
        CP_WAIT1();
        __syncthreads();
        const uint32_t kbase = ks_u + (uint32_t)((t & 1) * AQ_H * 2);
        const uint32_t vbase = vs_u + (uint32_t)((t & 1) * AQ_H * 2);
        const int* mb = m_s + (t & 1) * 64;

        // --- S = Q @ K^T  (fp16 mma, fp32 accum) ---
        float s[8][4];
        #pragma unroll
        for (int nt = 0; nt < 8; nt++)
            #pragma unroll
            for (int i = 0; i < 4; i++) s[nt][i] = 0.f;
        #pragma unroll
        for (int ks = 0; ks < 4; ks++) {
            uint32_t a0, a1, a2, a3;
            ldsm_x4(a0, a1, a2, a3, qs_u + q_lane + (uint32_t)(ks*32));
            #pragma unroll
            for (int p = 0; p < 4; p++) {
                uint32_t r0, r1, r2, r3;   // K rows n, cols k: non-trans
                ldsm_x4(r0, r1, r2, r3,
                    kbase + (uint32_t)(((p*16 + b_row_l)*QS + ks*16 + b_col_l) * 2));
                // r0: n0-7/k0-7, r1: n8-15/k0-7, r2: n0-7/k8-15, r3: n8-15/k8-15
                mma16(s[2*p],   a0, a1, a2, a3, r0, r2);
                mma16(s[2*p+1], a0, a1, a2, a3, r1, r3);
            }
        }

        // --- scale + mask + exp -> half2 P frags (registers only) ---
        uint32_t ph[8][2];
        #pragma unroll
        for (int nt = 0; nt < 8; nt++) {
            const int c0 = nt*8 + tig*2;
            const bool z0 = (mb[c0] == 0), z1 = (mb[c0+1] == 0);
            float p0 = __expf(z0 ? -1e9f : s[nt][0] * 0.125f);
            float p1 = __expf(z1 ? -1e9f : s[nt][1] * 0.125f);
            float p2 = __expf(z0 ? -1e9f : s[nt][2] * 0.125f);
            float p3 = __expf(z1 ? -1e9f : s[nt][3] * 0.125f);
            l0 += p0 + p1;  l1 += p2 + p3;
            ph[nt][0] = packh2(p0, p1);
            ph[nt][1] = packh2(p2, p3);
        }

        // --- O += P @ V  (P from registers; V trans ldsm) ---
        #pragma unroll
        for (int ks = 0; ks < 4; ks++) {
            uint32_t pa0 = ph[2*ks][0],   pa1 = ph[2*ks][1];
            uint32_t pa2 = ph[2*ks+1][0], pa3 = ph[2*ks+1][1];
            #pragma unroll
            for (int p = 0; p < 4; p++) {
                uint32_t r0, r1, r2, r3;   // V rows k, cols n: trans
                ldsm_x4_t(r0, r1, r2, r3,
                    vbase + (uint32_t)(((ks*16 + b_row_l)*QS + p*16 + b_col_l) * 2));
                // r0: k0-7/n0-7, r1: k8-15/n0-7, r2: k0-7/n8-15, r3: k8-15/n8-15
                mma16(o[2*p],   pa0, pa1, pa2, pa3, r0, r1);
                mma16(o[2*p+1], pa0, pa1, pa2, pa3, r2, r3);
            }
        }
        __syncthreads();     // done with stage t&1 before t+1 iter overwrites
    }

    l0 += __shfl_xor_sync(0xffffffffu, l0, 1);
    l0 += __shfl_xor_sync(0xffffffffu, l0, 2);
    l1 += __shfl_xor_sync(0xffffffffu, l1, 1);
    l1 += __shfl_xor_sync(0xffffffffu, l1, 2);
    const float n0 = 1.0f / l0, n1 = 1.0f / l1;
    #pragma unroll
    for (int nt = 0; nt < 8; nt++) {
        const int cn = h*DK + nt*8 + tig*2;
        size_t r0 = (size_t)(b*SQ + qt*64 + w*16 + gid) * DM + cn;
        size_t r1 = r0 + (size_t)8 * DM;
        *(uint32_t*)(O + r0) = packh2(o[nt][0]*n0, o[nt][1]*n0);
        *(uint32_t*)(O + r1) = packh2(o[nt][2]*n1, o[nt][3]*n1);
    }
}

// --------------------------------------------------------------------------
extern "C" void kernel_launch(void* const* d_in, const int* in_sizes, int n_in,
                              void* d_out, int out_size)
{
    const float* x    = (const float*)d_in[0];
    const int*   mask = (const int*)  d_in[1];
    const float* wq = (const float*)d_in[2],  *bq = (const float*)d_in[3];
    const float* wk = (const float*)d_in[4],  *bk = (const float*)d_in[5];
    const float* wv = (const float*)d_in[6],  *bv = (const float*)d_in[7];
    const float* wo = (const float*)d_in[8],  *bo = (const float*)d_in[9];
    const float* w1 = (const float*)d_in[10], *b1 = (const float*)d_in[11];
    const float* w2 = (const float*)d_in[12], *b2 = (const float*)d_in[13];
    const float* g1 = (const float*)d_in[14], *be1 = (const float*)d_in[15];
    const float* g2 = (const float*)d_in[16], *be2 = (const float*)d_in[17];
    float* out = (float*)d_out;

    __half *xn, *qkvh, *ctxh, *hbuf, *Wqh, *Wrh;
    float *x1, *Bq;
    cudaGetSymbolAddress((void**)&xn,   g_xn_h);
    cudaGetSymbolAddress((void**)&qkvh, g_qkv_h);
    cudaGetSymbolAddress((void**)&ctxh, g_ctx_h);
    cudaGetSymbolAddress((void**)&x1,   g_x1);
    cudaGetSymbolAddress((void**)&hbuf, g_h_h);
    cudaGetSymbolAddress((void**)&Wqh,  g_wqkvh);
    cudaGetSymbolAddress((void**)&Bq,   g_bqkv);
    cudaGetSymbolAddress((void**)&Wrh,  g_wrh);
    __half* wo_h = Wrh;
    __half* w1_h = Wrh + DM*DM;
    __half* w2_h = Wrh + DM*DM + DM*DFF;

    cudaFuncSetAttribute(gemm_tc<0>, cudaFuncAttributeMaxDynamicSharedMemorySize, GEMM_SMEM);
    cudaFuncSetAttribute(gemm_tc<1>, cudaFuncAttributeMaxDynamicSharedMemorySize, GEMM_SMEM);
    cudaFuncSetAttribute(gemm_tc<2>, cudaFuncAttributeMaxDynamicSharedMemorySize, GEMM_SMEM);
    cudaFuncSetAttribute(attn_tc,    cudaFuncAttributeMaxDynamicSharedMemorySize, ATT_SMEM);

    dim3 gQKV(DM3/128, ROWS/128);    // 24 x 32
    dim3 gProj(DM/128,  ROWS/128);   // 8 x 32
    dim3 gFF1 (DFF/128, ROWS/128);   // 32 x 32

    // 0) weight prep (half)
    pack_qkv<<<(3*(DM*DM/4) + 3*256 + 255)/256, 256>>>(wq, wk, wv, bq, bk, bv, Wqh, Bq);
    half_all<<<((NW4_WO + NW4_W1 + NW4_W2) + 255)/256, 256>>>(wo, w1, w2, Wrh);
    // 1) LN1 -> half
    ln_kernel<<<ROWS, 256>>>(x, g1, be1, xn);
    // 2) fused QKV projection (fp16 mma, half out)
    gemm_tc<0><<<gQKV, 128, GEMM_SMEM>>>(xn, Wqh, Bq, nullptr, qkvh, ROWS, DM3, DM);
    // 3) fused masked flash attention (fp16) -> ctx half
    attn_tc<<<dim3(SQ/64, NH, BATCH), 128, ATT_SMEM>>>(qkvh, mask, ctxh);
    // 4) out-proj + residual(x) -> x1 (f32)
    gemm_tc<2><<<gProj, 128, GEMM_SMEM>>>(ctxh, wo_h, bo, x, x1, ROWS, DM, DM);
    // 5) LN2 -> half
    ln_kernel<<<ROWS, 256>>>(x1, g2, be2, xn);
    // 6) FFN up + relu -> half
    gemm_tc<1><<<gFF1, 128, GEMM_SMEM>>>(xn, w1_h, b1, nullptr, hbuf, ROWS, DFF, DM);
    // 7) FFN down + residual(x1) -> out (f32)
    gemm_tc<2><<<gProj, 128, GEMM_SMEM>>>(hbuf, w2_h, b2, x1, out, ROWS, DM, DFF);
}